// round 7
// baseline (speedup 1.0000x reference)
#include <cuda_runtime.h>

#define B       8
#define A       49104
#define C       20
#define M       32
#define NANN    16
#define APB     64                        // anchors per block
#define THREADS 320                       // = APB*5 float4 columns
#define NBLK    ((A + APB - 1) / APB)     // 768
#define A5      (A * 5)                   // float4 cols per batch plane
#define LN2F    0.6931471805599453f

// ---- scratch (device globals; every slot written every call) ----
__device__ float g_pc[B][NBLK];
__device__ float g_pr[B][NBLK];
__device__ int   g_pn[B][NBLK];
__device__ int   g_count = 0;             // last block resets -> replay-invariant

__global__ void __launch_bounds__(THREADS, 4) k_fused(
    const float* __restrict__ cls_in,       // [B,A,C]
    const float* __restrict__ regressions,  // [B,A,4]
    const float* __restrict__ anchors,      // [1,A,4]
    const float* __restrict__ ema_in,       // [B,A,C]
    const float* __restrict__ ema_classes,  // [B,M]
    const float* __restrict__ ema_bboxes,   // [B,M,4]
    const int*   __restrict__ ema_counts,   // [B]
    const float* __restrict__ annotations,  // [B,N,5]
    float* __restrict__ out)
{
    __shared__ float4   s_e[B][THREADS];    // staged ema chunks (40 KB)
    __shared__ float4   s_cbox[B][M];       // compacted kept boxes (asc. m)
    __shared__ float    s_carea[B][M];
    __shared__ unsigned s_abits[B][2];      // assigned bitmask, bit = local anchor
    __shared__ float    s_rw[B];
    __shared__ int      s_nw[B];
    __shared__ float    s_c[10][8];
    __shared__ bool     s_last;

    const int tid  = threadIdx.x;
    const int lane = tid & 31;
    const int wrp  = tid >> 5;              // 0..9

    const int  fcol = blockIdx.x * THREADS + tid;  // global float4 col in a plane
    const int  idx0 = (fcol < A5) ? fcol : 0;

    // ===== Pass A (all warps): stream e once, build alpha sums, stage to smem =====
    const float4* e4 = (const float4*)ema_in;
    float4 S;
    {
        const float4* ep = e4 + idx0;
        float4 e0 = ep[0];
        S = e0;
        s_e[0][tid] = e0;
        #pragma unroll
        for (int b = 1; b < 8; b++) {
            float4 e = ep[(size_t)b * A5];
            S.x += e.x; S.y += e.y; S.z += e.z; S.w += e.w;
            s_e[b][tid] = e;
        }
    }
    const float ax = 0.4f + 0.9f * S.x;     // LN2 factored out to epilogue
    const float ay = 0.4f + 0.9f * S.y;
    const float az = 0.4f + 0.9f * S.z;
    const float aw2 = 0.4f + 0.9f * S.w;

    // ================= Phase 1 (warps 0..7): warp = batch =================
    if (wrp < 8) {
        const int b = wrp;

        // -- compact kept boxes (order-preserving => first-argmax semantics)
        float4 bb4 = ((const float4*)ema_bboxes)[b * M + lane];
        bool vld = lane < ema_counts[b];
        float cl = ema_classes[b * M + lane];
        bool mem = false;
        #pragma unroll
        for (int n = 0; n < NANN; n++)
            mem |= (cl == annotations[(b * NANN + n) * 5 + 4]);
        unsigned msk = __ballot_sync(0xffffffffu, vld && mem);
        int p = __popc(msk & ((1u << lane) - 1u));
        if ((msk >> lane) & 1u) {
            s_cbox[b][p]  = bb4;
            s_carea[b][p] = (bb4.z - bb4.x) * (bb4.w - bb4.y);
        }
        const int cnt = __popc(msk);        // uniform in warp
        __syncwarp();

        // -- IoU assignment over both anchor halves (division-free argmax)
        float racc = 0.f;
        int   np   = 0;
        #pragma unroll
        for (int h = 0; h < 2; h++) {
            const int aloc = h * 32 + lane;
            const int a = blockIdx.x * APB + aloc;
            const bool valid = (a < A);
            const float4 an = ((const float4*)anchors)[valid ? a : 0];
            const float aw = an.z - an.x, ah = an.w - an.y;
            const float acx = an.x + 0.5f * aw, acy = an.y + 0.5f * ah;
            const float area_a = aw * ah;

            float bI = -1.f, bU = 1.f;
            int   bi = 0;
            for (int m = 0; m < cnt; m++) {
                float4 bx = s_cbox[b][m];   // LDS broadcast
                float iw = fminf(an.z, bx.z) - fmaxf(an.x, bx.x);
                float ih = fminf(an.w, bx.w) - fmaxf(an.y, bx.y);
                iw = fmaxf(iw, 0.f);
                ih = fmaxf(ih, 0.f);
                float inter = iw * ih;
                float u = fmaxf(area_a + s_carea[b][m] - inter, 1e-8f);
                bool better = inter * bU > bI * u;   // iou > best (u,bU > 0)
                bi = better ? m : bi;
                bI = better ? inter : bI;
                bU = better ? u : bU;
            }
            const bool has = (cnt > 0) && valid;
            const bool pos = has && (bI >= 0.5f * bU);
            const bool assigned = has && ((bI < 0.4f * bU) || (bI >= 0.5f * bU));

            unsigned ab = __ballot_sync(0xffffffffu, assigned);
            unsigned pb = __ballot_sync(0xffffffffu, pos);
            if (lane == 0) s_abits[b][h] = ab;
            np += __popc(pb);

            if (pos) {
                float4 r = ((const float4*)regressions)[(size_t)b * A + a];
                float4 g = s_cbox[b][bi];
                float gw = g.z - g.x, gh = g.w - g.y;
                float gcx = g.x + 0.5f * gw, gcy = g.y + 0.5f * gh;
                gw = fmaxf(gw, 1.f);
                gh = fmaxf(gh, 1.f);
                float dx = (gcx - acx) / aw / 0.1f;
                float dy = (gcy - acy) / ah / 0.1f;
                float dw = __logf(gw / aw) / 0.2f;
                float dh = __logf(gh / ah) / 0.2f;
                float d;
                d = fabsf(dx - r.x); racc += (d <= 1.f/9.f) ? 4.5f*d*d : d - 0.5f/9.f;
                d = fabsf(dy - r.y); racc += (d <= 1.f/9.f) ? 4.5f*d*d : d - 0.5f/9.f;
                d = fabsf(dw - r.z); racc += (d <= 1.f/9.f) ? 4.5f*d*d : d - 0.5f/9.f;
                d = fabsf(dh - r.w); racc += (d <= 1.f/9.f) ? 4.5f*d*d : d - 0.5f/9.f;
            }
        }
        #pragma unroll
        for (int o = 16; o; o >>= 1) racc += __shfl_down_sync(0xffffffffu, racc, o);
        if (lane == 0) { s_rw[b] = racc; s_nw[b] = np; }
    }
    __syncthreads();

    // ===== Pass B: per-batch focal BCE (e from smem, c streamed from DRAM) =====
    const int aloc2 = tid / 5;                     // local anchor 0..63
    const int h2    = aloc2 >> 5;
    const int bit2  = aloc2 & 31;
    const float4* cp = (const float4*)cls_in + idx0;

    float cacc[8];
    #pragma unroll
    for (int b = 0; b < 8; b++) {
        float4 c = cp[(size_t)b * A5];
        float4 e = s_e[b][tid];
        float flag = (float)((s_abits[b][h2] >> bit2) & 1u);

        float t = 0.f;
        {
            float ec = fminf(fmaxf(e.x, 1e-4f), 1.f - 1e-4f);
            float cc = fminf(fmaxf(c.x, 1e-4f), 1.f - 1e-4f);
            float bce2 = -(ec * __log2f(cc) + (1.f - ec) * __log2f(1.f - cc));
            float d = ec - cc;
            t += ax * (d * d) * bce2;
        }
        {
            float ec = fminf(fmaxf(e.y, 1e-4f), 1.f - 1e-4f);
            float cc = fminf(fmaxf(c.y, 1e-4f), 1.f - 1e-4f);
            float bce2 = -(ec * __log2f(cc) + (1.f - ec) * __log2f(1.f - cc));
            float d = ec - cc;
            t += ay * (d * d) * bce2;
        }
        {
            float ec = fminf(fmaxf(e.z, 1e-4f), 1.f - 1e-4f);
            float cc = fminf(fmaxf(c.z, 1e-4f), 1.f - 1e-4f);
            float bce2 = -(ec * __log2f(cc) + (1.f - ec) * __log2f(1.f - cc));
            float d = ec - cc;
            t += az * (d * d) * bce2;
        }
        {
            float ec = fminf(fmaxf(e.w, 1e-4f), 1.f - 1e-4f);
            float cc = fminf(fmaxf(c.w, 1e-4f), 1.f - 1e-4f);
            float bce2 = -(ec * __log2f(cc) + (1.f - ec) * __log2f(1.f - cc));
            float d = ec - cc;
            t += aw2 * (d * d) * bce2;
        }
        cacc[b] = flag * t;
    }

    // per-warp reduce each batch accumulator, then cross-warp via smem
    #pragma unroll
    for (int b = 0; b < 8; b++) {
        float v = cacc[b];
        #pragma unroll
        for (int o = 16; o; o >>= 1) v += __shfl_xor_sync(0xffffffffu, v, o);
        cacc[b] = v;
    }
    if (lane == 0) {
        #pragma unroll
        for (int b = 0; b < 8; b++) s_c[wrp][b] = cacc[b];
    }
    __syncthreads();

    if (tid < 8) {
        float cs = 0.f;
        #pragma unroll
        for (int w = 0; w < 10; w++) cs += s_c[w][tid];
        g_pc[tid][blockIdx.x] = cs;
        g_pr[tid][blockIdx.x] = s_rw[tid];
        g_pn[tid][blockIdx.x] = s_nw[tid];
    }

    // ================= last-block final reduction =================
    __threadfence();
    __syncthreads();
    if (tid == 0) s_last = (atomicAdd(&g_count, 1) == (int)gridDim.x - 1);
    __syncthreads();
    if (!s_last) return;
    __threadfence();

    if (wrp < 8) {
        const int bb = wrp;
        float cs = 0.f, rs = 0.f;
        int   ns = 0;
        #pragma unroll 4
        for (int i = lane; i < NBLK; i += 32) {
            cs += g_pc[bb][i];
            rs += g_pr[bb][i];
            ns += g_pn[bb][i];
        }
        #pragma unroll
        for (int o = 16; o; o >>= 1) {
            cs += __shfl_down_sync(0xffffffffu, cs, o);
            rs += __shfl_down_sync(0xffffffffu, rs, o);
            ns += __shfl_down_sync(0xffffffffu, ns, o);
        }
        if (lane == 0) {
            float npf = (float)ns;
            float mx  = fmaxf(npf, 1.f);
            s_c[0][bb] = cs / mx;
            s_c[1][bb] = (npf > 0.f) ? rs / (4.f * mx) : 0.f;
        }
    }
    __syncthreads();
    if (tid == 0) {
        float cs = 0.f, rs = 0.f;
        #pragma unroll
        for (int bb = 0; bb < 8; bb++) { cs += s_c[0][bb]; rs += s_c[1][bb]; }
        out[0] = cs * (0.125f * LN2F);    // LN2 applied once here
        out[1] = rs * 0.125f;
        g_count = 0;
    }
}

extern "C" void kernel_launch(void* const* d_in, const int* in_sizes, int n_in,
                              void* d_out, int out_size) {
    const float* classifications     = (const float*)d_in[0];
    const float* regressions         = (const float*)d_in[1];
    const float* anchors             = (const float*)d_in[2];
    const float* ema_classifications = (const float*)d_in[3];
    const float* ema_classes         = (const float*)d_in[4];
    const float* ema_bboxes          = (const float*)d_in[5];
    const int*   ema_counts          = (const int*)d_in[6];
    const float* annotations         = (const float*)d_in[7];

    k_fused<<<NBLK, THREADS>>>(classifications, regressions, anchors,
                               ema_classifications, ema_classes, ema_bboxes,
                               ema_counts, annotations, (float*)d_out);
}